// round 17
// baseline (speedup 1.0000x reference)
#include <cuda_runtime.h>
#include <cuda_fp16.h>
#include <cstdint>
#include <math.h>

// ---------------------------------------------------------------- constants
#define B_ 4
#define S_ 8192
#define D_ 1024
#define H_ 1024
#define O_ 1024

#define BM 128                 // s-rows per CTA tile
#define BN 64                  // j-cols per CTA tile (per gate; 3 gates)
#define BK 64                  // k per pipeline chunk
#define NCHUNK (D_ / BK)       // 16
#define NTH 512                // 16 warps (4 per SMSP)

#define ROWB 144               // fp16 smem row stride bytes (128 data + 16 pad)
#define A_TILE (BM * ROWB)     // 18432 (one A16 buffer)
#define B_TILE (BN * ROWB)     // 9216
#define BSTAGE (3 * B_TILE)    // 27648 (3 gates)
#define B_OFF  (2 * A_TILE)    // 36864
#define SMEM_DYN (B_OFF + 4 * BSTAGE)   // 147456

#define MTILES (B_ * S_ / BM)  // 256
#define JTILES (H_ / BN)       // 16
#define MT_PER_B (S_ / BM)     // 64

// ---------------------------------------------------------------- scratch
__device__ __half g_wh[3 * H_ * D_];
__device__ float g_pacc[B_][MT_PER_B][H_];
__device__ float g_sig[B_][H_];
__device__ float g_hT[B_][H_];

// ---------------------------------------------------------------- helpers
__device__ __forceinline__ uint32_t smem_u32(const void* p) {
    uint32_t a;
    asm("{ .reg .u64 t; cvta.to.shared.u64 t, %1; cvt.u32.u64 %0, t; }"
        : "=r"(a) : "l"(p));
    return a;
}

__device__ __forceinline__ void cp_async16(uint32_t dst, const void* src) {
    size_t g = (size_t)__cvta_generic_to_global(src);
    asm volatile("cp.async.cg.shared.global [%0], [%1], 16;\n"
                 :: "r"(dst), "l"(g));
}

__device__ __forceinline__ void ldsm_x4(uint32_t* r, uint32_t addr) {
    asm volatile("ldmatrix.sync.aligned.m8n8.x4.shared.b16 {%0,%1,%2,%3}, [%4];"
                 : "=r"(r[0]), "=r"(r[1]), "=r"(r[2]), "=r"(r[3]) : "r"(addr));
}

__device__ __forceinline__ void mma16816(float* c, const uint32_t* a,
                                         uint32_t b0, uint32_t b1) {
    asm volatile(
        "mma.sync.aligned.m16n8k16.row.col.f32.f16.f16.f32 "
        "{%0,%1,%2,%3}, {%4,%5,%6,%7}, {%8,%9}, {%0,%1,%2,%3};"
        : "+f"(c[0]), "+f"(c[1]), "+f"(c[2]), "+f"(c[3])
        : "r"(a[0]), "r"(a[1]), "r"(a[2]), "r"(a[3]), "r"(b0), "r"(b1));
}

// ---------------------------------------------------------------- prep: w fp32 -> fp16
#define NW4 (3 * H_ * D_ / 4)      // 786432

__global__ __launch_bounds__(512) void k_cvt_w(const float* __restrict__ w) {
    int base = blockIdx.x * 2048 + threadIdx.x;
#pragma unroll
    for (int v = 0; v < 4; ++v) {
        int i = base + v * 512;
        if (i >= NW4) return;
        float4 u = ((const float4*)w)[i];
        unsigned short hb[4];
        hb[0] = __half_as_ushort(__float2half_rn(u.x));
        hb[1] = __half_as_ushort(__float2half_rn(u.y));
        hb[2] = __half_as_ushort(__float2half_rn(u.z));
        hb[3] = __half_as_ushort(__float2half_rn(u.w));
        uint2 hp;
        hp.x = (uint32_t)hb[0] | ((uint32_t)hb[1] << 16);
        hp.y = (uint32_t)hb[2] | ((uint32_t)hb[3] << 16);
        ((uint2*)g_wh)[i] = hp;
    }
}

// ---------------------------------------------------------------- B stage loader (fp16 w)
__device__ __forceinline__ void load_B(uint32_t sb0, int ck, int j0, int tid) {
    const int k0 = ck * BK;
    const uint32_t bb = sb0 + B_OFF + (ck & 3) * BSTAGE;
    // 3 gates x 64 rows x 8 chunks of 16B = 1536 cp.asyncs ; 3 per thread
#pragma unroll
    for (int it = 0; it < 3; ++it) {
        int idx = tid + it * NTH;
        int g = idx >> 9;
        int rr = idx & 511;
        int r = rr >> 3, c = rr & 7;
        const void* src = g_wh + (size_t)(g * H_ + j0 + r) * D_ + k0 + c * 8;
        cp_async16(bb + g * B_TILE + r * ROWB + c * 16, src);
    }
    asm volatile("cp.async.commit_group;" ::: "memory");
}

// ---------------------------------------------------------------- main fused cvt+GEMM+reduce
extern __shared__ __align__(128) char dynsmem[];

__global__ __launch_bounds__(NTH, 1) void k1_mma(const float* __restrict__ x) {
    __shared__ float jacc[4][BN];

    const int tid = threadIdx.x;
    const int wid = tid >> 5;
    const int lane = tid & 31;
    const int wm = wid >> 2;            // 0..3 (32 rows each)
    const int wn = wid & 3;             // 0..3 (16 cols each)
    const int jt = blockIdx.x;          // 0..15
    const int mt = blockIdx.y;          // 0..255
    const int b = mt >> 6;
    const int mtb = mt & 63;
    const int j0 = jt * BN;

    const uint32_t sb0 = smem_u32(dynsmem);
    const size_t xrow0 = (size_t)mt * BM * D_;

    // per-thread A ownership: 16 consecutive fp32 of one row per chunk
    const int ar = tid >> 2;            // row 0..127
    const int ac = tid & 3;             // 16-float group 0..3
    const float* xp = x + xrow0 + (size_t)ar * D_ + ac * 16;
    const uint32_t a_dst_base = sb0 + ar * ROWB + ac * 32;

    float4 rA[4];                       // register-held raw A fp32 (one chunk)

    float acc[3][2][2][4];
#pragma unroll
    for (int g = 0; g < 3; ++g)
#pragma unroll
        for (int mf = 0; mf < 2; ++mf)
#pragma unroll
            for (int nf = 0; nf < 2; ++nf)
#pragma unroll
                for (int q = 0; q < 4; ++q) acc[g][mf][nf][q] = 0.0f;

    // ---- prologue
#pragma unroll
    for (int q = 0; q < 4; ++q) rA[q] = *(const float4*)(xp + q * 4);
    load_B(sb0, 0, j0, tid);
    load_B(sb0, 1, j0, tid);
    load_B(sb0, 2, j0, tid);
    {   // cvt chunk 0 -> A16[0]
        __half2 h[8];
#pragma unroll
        for (int q = 0; q < 4; ++q) {
            h[q * 2 + 0] = __floats2half2_rn(rA[q].x, rA[q].y);
            h[q * 2 + 1] = __floats2half2_rn(rA[q].z, rA[q].w);
        }
        asm volatile("st.shared.v4.b32 [%0], {%1,%2,%3,%4};"
                     :: "r"(a_dst_base), "r"(*(uint32_t*)&h[0]),
                        "r"(*(uint32_t*)&h[1]), "r"(*(uint32_t*)&h[2]),
                        "r"(*(uint32_t*)&h[3]));
        asm volatile("st.shared.v4.b32 [%0], {%1,%2,%3,%4};"
                     :: "r"(a_dst_base + 16), "r"(*(uint32_t*)&h[4]),
                        "r"(*(uint32_t*)&h[5]), "r"(*(uint32_t*)&h[6]),
                        "r"(*(uint32_t*)&h[7]));
    }
#pragma unroll
    for (int q = 0; q < 4; ++q) rA[q] = *(const float4*)(xp + BK + q * 4);

    const uint32_t a_rowsel = (wm * 32 + (lane & 15)) * ROWB +
                              ((lane >> 4) << 4);
    const uint32_t b_rowsel = (wn * 16 + (lane & 15)) * ROWB +
                              ((lane >> 4) << 4);

    for (int ck = 0; ck < NCHUNK; ++ck) {
        if (ck <= NCHUNK - 3) {
            asm volatile("cp.async.wait_group 2;" ::: "memory");
        } else if (ck == NCHUNK - 2) {
            asm volatile("cp.async.wait_group 1;" ::: "memory");
        } else {
            asm volatile("cp.async.wait_group 0;" ::: "memory");
        }
        __syncthreads();

        // convert chunk ck+1 (regs) -> A16[(ck+1)&1]; then LDG chunk ck+2
        if (ck + 1 < NCHUNK) {
            __half2 h[8];
#pragma unroll
            for (int q = 0; q < 4; ++q) {
                h[q * 2 + 0] = __floats2half2_rn(rA[q].x, rA[q].y);
                h[q * 2 + 1] = __floats2half2_rn(rA[q].z, rA[q].w);
            }
            uint32_t dst = a_dst_base + ((ck + 1) & 1) * A_TILE;
            asm volatile("st.shared.v4.b32 [%0], {%1,%2,%3,%4};"
                         :: "r"(dst), "r"(*(uint32_t*)&h[0]),
                            "r"(*(uint32_t*)&h[1]), "r"(*(uint32_t*)&h[2]),
                            "r"(*(uint32_t*)&h[3]));
            asm volatile("st.shared.v4.b32 [%0], {%1,%2,%3,%4};"
                         :: "r"(dst + 16), "r"(*(uint32_t*)&h[4]),
                            "r"(*(uint32_t*)&h[5]), "r"(*(uint32_t*)&h[6]),
                            "r"(*(uint32_t*)&h[7]));
        }
        if (ck + 2 < NCHUNK) {
#pragma unroll
            for (int q = 0; q < 4; ++q)
                rA[q] = *(const float4*)(xp + (ck + 2) * BK + q * 4);
        }
        if (ck + 3 < NCHUNK)
            load_B(sb0, ck + 3, j0, tid);

        const uint32_t abuf = sb0 + (ck & 1) * A_TILE;
        const uint32_t bbuf = sb0 + B_OFF + (ck & 3) * BSTAGE;

#pragma unroll
        for (int ks = 0; ks < 4; ++ks) {
            const uint32_t koff = ks * 32;
            uint32_t ah[2][4];
#pragma unroll
            for (int mf = 0; mf < 2; ++mf)
                ldsm_x4(ah[mf], abuf + a_rowsel + mf * (16 * ROWB) + koff);
#pragma unroll
            for (int g = 0; g < 3; ++g) {
                uint32_t bq[4];   // r0=nf0.b0 r1=nf1.b0 r2=nf0.b1 r3=nf1.b1
                ldsm_x4(bq, bbuf + g * B_TILE + b_rowsel + koff);
#pragma unroll
                for (int mf = 0; mf < 2; ++mf) {
                    mma16816(acc[g][mf][0], ah[mf], bq[0], bq[2]);
                    mma16816(acc[g][mf][1], ah[mf], bq[1], bq[3]);
                }
            }
        }
    }

    // ---- epilogue: elementwise + reduce over s rows
    float vloc[2][2] = {{0.f, 0.f}, {0.f, 0.f}};   // [nf][q&1]
#pragma unroll
    for (int mf = 0; mf < 2; ++mf)
#pragma unroll
        for (int nf = 0; nf < 2; ++nf)
#pragma unroll
            for (int q = 0; q < 4; ++q) {
                float zf = acc[0][mf][nf][q];
                float zi = acc[1][mf][nf][q];
                float zh = acc[2][mf][nf][q];
                float R = __fdividef(1.0f + __expf(-zf),
                                     1.0f + __expf(-zi));   // exp(diff)
                float gv = (zh >= 0.0f)
                               ? (zh + 0.5f)
                               : __fdividef(1.0f, 1.0f + __expf(-zh));
                vloc[nf][q & 1] += R * gv;
                int row = wm * 32 + mf * 16 + (lane >> 2) + ((q >> 1) << 3);
                if (((mt * BM + row) & (S_ - 1)) == (S_ - 1)) {
                    int j = j0 + wn * 16 + nf * 8 + (lane & 3) * 2 + (q & 1);
                    g_sig[b][j] = __fdividef(1.0f, 1.0f + R);
                }
            }
#pragma unroll
    for (int nf = 0; nf < 2; ++nf)
#pragma unroll
        for (int q1 = 0; q1 < 2; ++q1) {
            float v = vloc[nf][q1];
            v += __shfl_xor_sync(0xffffffffu, v, 4);
            v += __shfl_xor_sync(0xffffffffu, v, 8);
            v += __shfl_xor_sync(0xffffffffu, v, 16);
            if (lane < 4) jacc[wm][wn * 16 + nf * 8 + lane * 2 + q1] = v;
        }
    __syncthreads();
    if (tid < BN)
        g_pacc[b][mtb][j0 + tid] =
            jacc[0][tid] + jacc[1][tid] + jacc[2][tid] + jacc[3][tid];
}

// ---------------------------------------------------------------- combine + out-init
__global__ __launch_bounds__(128) void k2_combine(const float* __restrict__ b_out,
                                                  float* __restrict__ out) {
    int b = blockIdx.x >> 3;
    int j = (blockIdx.x & 7) * 128 + threadIdx.x;
    float s = 0.0f;
#pragma unroll
    for (int mtb = 0; mtb < MT_PER_B; ++mtb) s += g_pacc[b][mtb][j];
    g_hT[b][j] = g_sig[b][j] * (0.5f + s);
    out[(size_t)b * O_ + j] = b_out[j];   // bias init for k3's atomics
}

// ---------------------------------------------------------------- out += hT @ w_out^T (k-split, atomic)
#define KS 16
#define KCH (H_ / KS)          // 64 k per split

__global__ __launch_bounds__(128) void k3_out(const float* __restrict__ w_out,
                                              float* __restrict__ out) {
    int o = blockIdx.x * 128 + threadIdx.x;
    int b = blockIdx.y;
    int k0 = blockIdx.z * KCH;

    __shared__ float hs[KCH];
    if (threadIdx.x < KCH) hs[threadIdx.x] = g_hT[b][k0 + threadIdx.x];
    __syncthreads();

    float acc = 0.0f;
    const float4* wr = (const float4*)(w_out + (size_t)o * H_ + k0);
#pragma unroll
    for (int q = 0; q < KCH / 4; ++q) {
        float4 w4 = wr[q];
        float4 h4 = *(const float4*)&hs[q * 4];
        acc = fmaf(w4.x, h4.x, acc);
        acc = fmaf(w4.y, h4.y, acc);
        acc = fmaf(w4.z, h4.z, acc);
        acc = fmaf(w4.w, h4.w, acc);
    }
    atomicAdd(&out[(size_t)b * O_ + o], acc);
}

// ---------------------------------------------------------------- launch
extern "C" void kernel_launch(void* const* d_in, const int* in_sizes, int n_in,
                              void* d_out, int out_size) {
    (void)in_sizes; (void)n_in; (void)out_size;
    const float* x     = (const float*)d_in[0];   // [4, 8192, 1024]
    const float* w_in  = (const float*)d_in[1];   // [3072, 1024]
    const float* w_out = (const float*)d_in[2];   // [1024, 1024]
    const float* b_out = (const float*)d_in[3];   // [1024]
    float* out = (float*)d_out;                   // [4, 1024]

    static int smem_set = 0;
    if (!smem_set) {
        cudaFuncSetAttribute(k1_mma, cudaFuncAttributeMaxDynamicSharedMemorySize,
                             SMEM_DYN);
        smem_set = 1;
    }

    k_cvt_w<<<(NW4 + 2047) / 2048, 512>>>(w_in);

    dim3 g1(JTILES, MTILES);
    k1_mma<<<g1, NTH, SMEM_DYN>>>(x);
    k2_combine<<<B_ * 8, 128>>>(b_out, out);
    dim3 g3(O_ / 128, B_, KS);
    k3_out<<<g3, 128>>>(w_out, out);
}